// round 15
// baseline (speedup 1.0000x reference)
#include <cuda_runtime.h>

// MN neuron scan: T=1000 steps, B*N = 32768 independent neurons.
//
// R14 = R7 (best: 88.6us) + scheduler-pressure fixes.
// Evidence: per-warp cost tracks "33 serial links x 4cyc" in every config;
// true dataflow depth is ~15 links. ptxas is serializing subchains, and the
// R7(96reg)->R12(72reg) regression says register budget is the cause.
//  - UPF=5 (was 10): prefetch buffers 40->20 regs, unrolled body halves
//    -> more reg headroom & smaller scheduling window. Distance still
//    10 steps (~1650 cyc) > ~1050-cyc NAT DRAM latency.
//  - spike test: direct (V > Thr) FSETP, dropping the vm=V-Thr FFMA.
//    Exactly equivalent: float compare is exact; rn(V-Thr)>0 <=> V>Thr
//    (non-FTZ subtraction of distinct floats can't round to zero).
//  - Everything else identical to R7: block 32, launch_bounds(32),
//    2 neurons/thread, two sequential step_one calls, burst prefetch.
// All arithmetic is fma.rn.f32 via inline asm (a+b==fma(a,1,b),
// a*k==fma(a,k,-0.0)) preserving XLA's uncontracted per-op IEEE rounding
// (validated bit-exact: rel_err 0.0 in R6/R7/R8/R11/R12).

#define T_STEPS 1000
#define NN      512
#define BN      32768          // B * N
#define NT      (BN / 2)       // threads (2 neurons each)
#define UPF     5              // steps per prefetch group

__device__ __forceinline__ float ffma(float a, float b, float c) {
    float d;
    asm("fma.rn.f32 %0, %1, %2, %3;" : "=f"(d) : "f"(a), "f"(b), "f"(c));
    return d;
}

struct NState { float V, i1, i2, Thr; };

// One bit-exact reference step for one neuron. Returns spike (0/1).
__device__ __forceinline__ float step_one(NState& s, float xt,
                                          float lw, float av,
                                          float A1v, float A2v)
{
    const float VR   = -0.07f;
    const float TR   = -0.06f;
    const float NEL  =  0.07f;   // -EL
    const float NTIN =  0.05f;   // -TINF
    const float DT   = 0.01f;
    const float K1   = 200.0f;
    const float K2   = 20.0f;
    const float Gc   = 45.24007797241211f;
    const float Bc   = 12.77495288848877f;
    const float R1   = 0.3858567178249359f;
    const float R2   = -1.1421641111373901f;
    const float NZ   = -0.0f;

    // i1 -= (K1*i1)*DT ; i2 -= (K2*i2)*DT
    float m1 = ffma(s.i1, K1, NZ); m1 = ffma(m1, DT, NZ); s.i1 = ffma(m1, -1.0f, s.i1);
    float m2 = ffma(s.i2, K2, NZ); m2 = ffma(m2, DT, NZ); s.i2 = ffma(m2, -1.0f, s.i2);

    // V += DT * (((lin*xt + i1) + i2) - G*(V-EL))
    float lx  = ffma(lw, xt, NZ);
    float ss  = ffma(lx, 1.0f, s.i1);
    ss        = ffma(ss, 1.0f, s.i2);
    float vel = ffma(s.V, 1.0f, NEL);
    float gq  = ffma(vel, Gc, NZ);
    float dv  = ffma(gq, -1.0f, ss);
    dv        = ffma(dv, DT, NZ);
    s.V       = ffma(dv, 1.0f, s.V);

    // Thr += DT * (a*(V-EL) - B*(Thr-TINF))
    float ve2 = ffma(s.V, 1.0f, NEL);
    float t1  = ffma(av, ve2, NZ);
    float tt  = ffma(s.Thr, 1.0f, NTIN);
    float t2  = ffma(tt, Bc, NZ);
    float dd  = ffma(t2, -1.0f, t1);
    dd        = ffma(dd, DT, NZ);
    s.Thr     = ffma(dd, 1.0f, s.Thr);

    // spk = (V - Thr) > 0  <=>  V > Thr  (exact; saves one FFMA on the chain)
    const bool p = (s.V > s.Thr);

    // resets (spk in {0,1} -> exact selects)
    float i1n = ffma(ffma(s.i1, R1, NZ), 1.0f, A1v);
    float i2n = ffma(ffma(s.i2, R2, NZ), 1.0f, A2v);
    s.i1  = p ? i1n : s.i1;
    s.i2  = p ? i2n : s.i2;
    s.Thr = p ? fmaxf(s.Thr, TR) : s.Thr;
    s.V   = p ? VR : s.V;
    return p ? 1.0f : 0.0f;
}

__global__ __launch_bounds__(32)
void mn_neuron_kernel(const float* __restrict__ x,
                      const float* __restrict__ lin,
                      const float* __restrict__ aarr,
                      const float* __restrict__ A1arr,
                      const float* __restrict__ A2arr,
                      float* __restrict__ out)
{
    const int gid = blockIdx.x * 32 + threadIdx.x;   // pair id in [0, NT)
    const int n0  = (2 * gid) & (NN - 1);            // even; n1 = n0+1

    // Parameters for the pair (vectorized; n0 even -> 8B aligned)
    const float2 l2  = *(const float2*)(lin   + n0);
    const float2 a2  = *(const float2*)(aarr  + n0);
    const float2 A12 = *(const float2*)(A1arr + n0);
    const float2 A22 = *(const float2*)(A2arr + n0);

    NState s0 = { -0.07f, 0.0f, 0.0f, -0.05f };
    NState s1 = { -0.07f, 0.0f, 0.0f, -0.05f };

    const float2* xp = (const float2*)x   + gid;     // stride BN/2 float2 per step
    float2*       op = (float2*)      out + gid;

    // Prime two prefetch groups (10 LDG.64 in flight, 10-step distance)
    float2 bufA[UPF], bufB[UPF];
#pragma unroll
    for (int u = 0; u < UPF; ++u) bufA[u] = xp[(size_t)u * (BN / 2)];
#pragma unroll
    for (int u = 0; u < UPF; ++u) bufB[u] = xp[(size_t)(UPF + u) * (BN / 2)];

    for (int t0 = 0; t0 < T_STEPS; t0 += 2 * UPF) {
        // ---- phase A: consume bufA (steps t0 .. t0+UPF-1) ----
        float2 cur[UPF];
#pragma unroll
        for (int u = 0; u < UPF; ++u) cur[u] = bufA[u];
        if (t0 + 2 * UPF < T_STEPS) {
            const float2* np = xp + (size_t)(t0 + 2 * UPF) * (BN / 2);
#pragma unroll
            for (int u = 0; u < UPF; ++u) bufA[u] = np[(size_t)u * (BN / 2)];
        }
#pragma unroll
        for (int u = 0; u < UPF; ++u) {
            float2 sp;
            sp.x = step_one(s0, cur[u].x, l2.x, a2.x, A12.x, A22.x);
            sp.y = step_one(s1, cur[u].y, l2.y, a2.y, A12.y, A22.y);
            op[(size_t)(t0 + u) * (BN / 2)] = sp;
        }

        // ---- phase B: consume bufB (steps t0+UPF .. t0+2*UPF-1) ----
#pragma unroll
        for (int u = 0; u < UPF; ++u) cur[u] = bufB[u];
        if (t0 + 3 * UPF < T_STEPS) {
            const float2* np = xp + (size_t)(t0 + 3 * UPF) * (BN / 2);
#pragma unroll
            for (int u = 0; u < UPF; ++u) bufB[u] = np[(size_t)u * (BN / 2)];
        }
#pragma unroll
        for (int u = 0; u < UPF; ++u) {
            float2 sp;
            sp.x = step_one(s0, cur[u].x, l2.x, a2.x, A12.x, A22.x);
            sp.y = step_one(s1, cur[u].y, l2.y, a2.y, A12.y, A22.y);
            op[(size_t)(t0 + UPF + u) * (BN / 2)] = sp;
        }
    }
}

extern "C" void kernel_launch(void* const* d_in, const int* in_sizes, int n_in,
                              void* d_out, int out_size)
{
    const float* x   = (const float*)d_in[0];  // [T, B, N]
    const float* lin = (const float*)d_in[1];  // [1, N]
    const float* a   = (const float*)d_in[2];  // [1, N]
    const float* A1  = (const float*)d_in[3];  // [1, N]
    const float* A2  = (const float*)d_in[4];  // [1, N]
    float* out = (float*)d_out;                // [T, B, N]

    (void)in_sizes; (void)n_in; (void)out_size;

    mn_neuron_kernel<<<NT / 32, 32>>>(x, lin, a, A1, A2, out);
}

// round 16
// speedup vs baseline: 1.2056x; 1.2056x over previous
#include <cuda_runtime.h>

// MN neuron scan: T=1000 steps, B*N = 32768 independent neurons.
//
// R15 = R7 (best: 88.6us) with DOUBLE the memory-level parallelism.
// Post-mortem evidence: dur tracks loads-in-flight/warp across all rounds
// (10 -> ~103-122us, 20 -> 88.6us); Little's law on R7 gives effective DRAM
// latency ~1650 cyc @NAT -> the kernel is memory-LATENCY-bound via MLP,
// not scheduler-bound (R14 falsified the register-pressure theory).
//  - UPF=20, ping-pong groups: up to 40 LDG.64 outstanding per warp
//    (M_max ~55), 40-step issue-to-consume distance, 1000/40=25 iterations.
//  - cur-copy + front-batched refill preserved (it issues the whole next
//    group's loads BEFORE the compute phase, building MLP early).
//  - block 32, 2 neurons/thread, direct (V > Thr) compare (exact; validated).
// All arithmetic is fma.rn.f32 via inline asm (a+b==fma(a,1,b),
// a*k==fma(a,k,-0.0)): FFMA-imm throughput while preserving XLA's
// uncontracted per-op IEEE rounding (rel_err 0.0 in every passing round).

#define T_STEPS 1000
#define NN      512
#define BN      32768          // B * N
#define NT      (BN / 2)       // threads (2 neurons each)
#define UPF     20             // steps per prefetch group (ping-pong x2)

__device__ __forceinline__ float ffma(float a, float b, float c) {
    float d;
    asm("fma.rn.f32 %0, %1, %2, %3;" : "=f"(d) : "f"(a), "f"(b), "f"(c));
    return d;
}

struct NState { float V, i1, i2, Thr; };

// One bit-exact reference step for one neuron. Returns spike (0/1).
__device__ __forceinline__ float step_one(NState& s, float xt,
                                          float lw, float av,
                                          float A1v, float A2v)
{
    const float VR   = -0.07f;
    const float TR   = -0.06f;
    const float NEL  =  0.07f;   // -EL
    const float NTIN =  0.05f;   // -TINF
    const float DT   = 0.01f;
    const float K1   = 200.0f;
    const float K2   = 20.0f;
    const float Gc   = 45.24007797241211f;
    const float Bc   = 12.77495288848877f;
    const float R1   = 0.3858567178249359f;
    const float R2   = -1.1421641111373901f;
    const float NZ   = -0.0f;

    // i1 -= (K1*i1)*DT ; i2 -= (K2*i2)*DT
    float m1 = ffma(s.i1, K1, NZ); m1 = ffma(m1, DT, NZ); s.i1 = ffma(m1, -1.0f, s.i1);
    float m2 = ffma(s.i2, K2, NZ); m2 = ffma(m2, DT, NZ); s.i2 = ffma(m2, -1.0f, s.i2);

    // V += DT * (((lin*xt + i1) + i2) - G*(V-EL))
    float lx  = ffma(lw, xt, NZ);
    float ss  = ffma(lx, 1.0f, s.i1);
    ss        = ffma(ss, 1.0f, s.i2);
    float vel = ffma(s.V, 1.0f, NEL);
    float gq  = ffma(vel, Gc, NZ);
    float dv  = ffma(gq, -1.0f, ss);
    dv        = ffma(dv, DT, NZ);
    s.V       = ffma(dv, 1.0f, s.V);

    // Thr += DT * (a*(V-EL) - B*(Thr-TINF))
    float ve2 = ffma(s.V, 1.0f, NEL);
    float t1  = ffma(av, ve2, NZ);
    float tt  = ffma(s.Thr, 1.0f, NTIN);
    float t2  = ffma(tt, Bc, NZ);
    float dd  = ffma(t2, -1.0f, t1);
    dd        = ffma(dd, DT, NZ);
    s.Thr     = ffma(dd, 1.0f, s.Thr);

    // spk = (V - Thr) > 0  <=>  V > Thr  (exact)
    const bool p = (s.V > s.Thr);

    // resets (spk in {0,1} -> exact selects)
    float i1n = ffma(ffma(s.i1, R1, NZ), 1.0f, A1v);
    float i2n = ffma(ffma(s.i2, R2, NZ), 1.0f, A2v);
    s.i1  = p ? i1n : s.i1;
    s.i2  = p ? i2n : s.i2;
    s.Thr = p ? fmaxf(s.Thr, TR) : s.Thr;
    s.V   = p ? VR : s.V;
    return p ? 1.0f : 0.0f;
}

__global__ __launch_bounds__(32)
void mn_neuron_kernel(const float* __restrict__ x,
                      const float* __restrict__ lin,
                      const float* __restrict__ aarr,
                      const float* __restrict__ A1arr,
                      const float* __restrict__ A2arr,
                      float* __restrict__ out)
{
    const int gid = blockIdx.x * 32 + threadIdx.x;   // pair id in [0, NT)
    const int n0  = (2 * gid) & (NN - 1);            // even; n1 = n0+1

    // Parameters for the pair (vectorized; n0 even -> 8B aligned)
    const float2 l2  = *(const float2*)(lin   + n0);
    const float2 a2  = *(const float2*)(aarr  + n0);
    const float2 A12 = *(const float2*)(A1arr + n0);
    const float2 A22 = *(const float2*)(A2arr + n0);

    NState s0 = { -0.07f, 0.0f, 0.0f, -0.05f };
    NState s1 = { -0.07f, 0.0f, 0.0f, -0.05f };

    const float2* xp = (const float2*)x   + gid;     // stride BN/2 float2 per step
    float2*       op = (float2*)      out + gid;

    // Prime two prefetch groups (40 LDG.64 in flight, 40-step distance)
    float2 bufA[UPF], bufB[UPF];
#pragma unroll
    for (int u = 0; u < UPF; ++u) bufA[u] = xp[(size_t)u * (BN / 2)];
#pragma unroll
    for (int u = 0; u < UPF; ++u) bufB[u] = xp[(size_t)(UPF + u) * (BN / 2)];

    for (int t0 = 0; t0 < T_STEPS; t0 += 2 * UPF) {
        // ---- phase A: consume bufA (steps t0 .. t0+UPF-1) ----
        float2 cur[UPF];
#pragma unroll
        for (int u = 0; u < UPF; ++u) cur[u] = bufA[u];
        if (t0 + 2 * UPF < T_STEPS) {
            const float2* np = xp + (size_t)(t0 + 2 * UPF) * (BN / 2);
#pragma unroll
            for (int u = 0; u < UPF; ++u) bufA[u] = np[(size_t)u * (BN / 2)];
        }
#pragma unroll
        for (int u = 0; u < UPF; ++u) {
            float2 sp;
            sp.x = step_one(s0, cur[u].x, l2.x, a2.x, A12.x, A22.x);
            sp.y = step_one(s1, cur[u].y, l2.y, a2.y, A12.y, A22.y);
            op[(size_t)(t0 + u) * (BN / 2)] = sp;
        }

        // ---- phase B: consume bufB (steps t0+UPF .. t0+2*UPF-1) ----
#pragma unroll
        for (int u = 0; u < UPF; ++u) cur[u] = bufB[u];
        if (t0 + 3 * UPF < T_STEPS) {
            const float2* np = xp + (size_t)(t0 + 3 * UPF) * (BN / 2);
#pragma unroll
            for (int u = 0; u < UPF; ++u) bufB[u] = np[(size_t)u * (BN / 2)];
        }
#pragma unroll
        for (int u = 0; u < UPF; ++u) {
            float2 sp;
            sp.x = step_one(s0, cur[u].x, l2.x, a2.x, A12.x, A22.x);
            sp.y = step_one(s1, cur[u].y, l2.y, a2.y, A12.y, A22.y);
            op[(size_t)(t0 + UPF + u) * (BN / 2)] = sp;
        }
    }
}

extern "C" void kernel_launch(void* const* d_in, const int* in_sizes, int n_in,
                              void* d_out, int out_size)
{
    const float* x   = (const float*)d_in[0];  // [T, B, N]
    const float* lin = (const float*)d_in[1];  // [1, N]
    const float* a   = (const float*)d_in[2];  // [1, N]
    const float* A1  = (const float*)d_in[3];  // [1, N]
    const float* A2  = (const float*)d_in[4];  // [1, N]
    float* out = (float*)d_out;                // [T, B, N]

    (void)in_sizes; (void)n_in; (void)out_size;

    mn_neuron_kernel<<<NT / 32, 32>>>(x, lin, a, A1, A2, out);
}

// round 17
// speedup vs baseline: 1.4105x; 1.1700x over previous
#include <cuda_runtime.h>

// MN neuron scan: T=1000 steps, B*N = 32768 independent neurons.
//
// R16 = R7 skeleton (best: 88.6us — block 32, 2 neurons/thread, UPF=10
// ping-pong burst prefetch, ~20 LDG.64 in flight) + scheduling fixes ONLY:
//  - The two neurons' steps are fused into one straight-line block with
//    strictly ALTERNATING ops. Dataflow critical path is ~50 cyc/step but we
//    measure 165: ptxas serializes the two sequential step_one() calls.
//    Alternating at source gives every stall-4 slot of chain A an
//    independent chain-B op. (R12's interleave test was confounded by
//    block128 + rolling reload; this isolates it on the best skeleton.)
//  - Direct (V > Thr) compare: exact (validated rel_err 0.0 in R14/R15),
//    one FFMA off the loop-carried path.
//  - __ldcs/__stcs on x/out: both are 131MB touch-once streams; evict-first
//    stops them churning L2.
// All arithmetic fma.rn.f32 via inline asm (a+b==fma(a,1,b), a*k==fma(a,k,-0.0)):
// preserves XLA's uncontracted per-op IEEE rounding (bit-exact every round).

#define T_STEPS 1000
#define NN      512
#define BN      32768          // B * N
#define NT      (BN / 2)       // threads (2 neurons each)
#define UPF     10             // steps per prefetch group (ping-pong x2)

__device__ __forceinline__ float ffma(float a, float b, float c) {
    float d;
    asm("fma.rn.f32 %0, %1, %2, %3;" : "=f"(d) : "f"(a), "f"(b), "f"(c));
    return d;
}

__global__ __launch_bounds__(32)
void mn_neuron_kernel(const float* __restrict__ x,
                      const float* __restrict__ lin,
                      const float* __restrict__ aarr,
                      const float* __restrict__ A1arr,
                      const float* __restrict__ A2arr,
                      float* __restrict__ out)
{
    const int gid = blockIdx.x * 32 + threadIdx.x;   // pair id in [0, NT)
    const int n0  = (2 * gid) & (NN - 1);            // even; n1 = n0+1

    const float VR   = -0.07f;
    const float TR   = -0.06f;
    const float NEL  =  0.07f;   // -EL
    const float NTIN =  0.05f;   // -TINF
    const float DT   = 0.01f;
    const float K1   = 200.0f;
    const float K2   = 20.0f;
    const float Gc   = 45.24007797241211f;
    const float Bc   = 12.77495288848877f;
    const float R1   = 0.3858567178249359f;
    const float R2   = -1.1421641111373901f;
    const float NZ   = -0.0f;

    // Parameters for the pair (vectorized; n0 even -> 8B aligned)
    const float2 l2  = *(const float2*)(lin   + n0);
    const float2 a2  = *(const float2*)(aarr  + n0);
    const float2 A12 = *(const float2*)(A1arr + n0);
    const float2 A22 = *(const float2*)(A2arr + n0);

    // State, two independent neurons (a/b)
    float Va = -0.07f, i1a = 0.0f, i2a = 0.0f, Ta = -0.05f;
    float Vb = -0.07f, i1b = 0.0f, i2b = 0.0f, Tb = -0.05f;

    const float2* xp = (const float2*)x   + gid;     // stride BN/2 per step
    float2*       op = (float2*)      out + gid;

    // Prime two prefetch groups (20 LDG.64 in flight, 20-step distance)
    float2 bufA[UPF], bufB[UPF];
#pragma unroll
    for (int u = 0; u < UPF; ++u) bufA[u] = __ldcs(xp + (size_t)u * (BN / 2));
#pragma unroll
    for (int u = 0; u < UPF; ++u) bufB[u] = __ldcs(xp + (size_t)(UPF + u) * (BN / 2));

    for (int t0 = 0; t0 < T_STEPS; t0 += 2 * UPF) {
        float2 cur[UPF];

#pragma unroll
        for (int ph = 0; ph < 2; ++ph) {
            // snapshot group, burst-refill it for t0 + 2*UPF (+ph*UPF)
#pragma unroll
            for (int u = 0; u < UPF; ++u) cur[u] = (ph == 0) ? bufA[u] : bufB[u];
            const int tn = t0 + (2 + ph) * UPF;
            if (tn < T_STEPS) {
                const float2* np = xp + (size_t)tn * (BN / 2);
#pragma unroll
                for (int u = 0; u < UPF; ++u) {
                    float2 v = __ldcs(np + (size_t)u * (BN / 2));
                    if (ph == 0) bufA[u] = v; else bufB[u] = v;
                }
            }

#pragma unroll
            for (int u = 0; u < UPF; ++u) {
                const float xa = cur[u].x, xb = cur[u].y;

                // ---- one step, both neurons, ops strictly alternating ----
                // i decays: i -= (K*i)*DT
                float m1a = ffma(i1a, K1, NZ);      float m1b = ffma(i1b, K1, NZ);
                float m2a = ffma(i2a, K2, NZ);      float m2b = ffma(i2b, K2, NZ);
                m1a = ffma(m1a, DT, NZ);            m1b = ffma(m1b, DT, NZ);
                m2a = ffma(m2a, DT, NZ);            m2b = ffma(m2b, DT, NZ);
                i1a = ffma(m1a, -1.0f, i1a);        i1b = ffma(m1b, -1.0f, i1b);
                i2a = ffma(m2a, -1.0f, i2a);        i2b = ffma(m2b, -1.0f, i2b);

                // V += DT * (((lin*xt + i1) + i2) - G*(V-EL))
                float lxa = ffma(l2.x, xa, NZ);     float lxb = ffma(l2.y, xb, NZ);
                float vea = ffma(Va, 1.0f, NEL);    float veb = ffma(Vb, 1.0f, NEL);
                float sa  = ffma(lxa, 1.0f, i1a);   float sb  = ffma(lxb, 1.0f, i1b);
                float gqa = ffma(vea, Gc, NZ);      float gqb = ffma(veb, Gc, NZ);
                sa        = ffma(sa, 1.0f, i2a);    sb        = ffma(sb, 1.0f, i2b);
                float dva = ffma(gqa, -1.0f, sa);   float dvb = ffma(gqb, -1.0f, sb);
                dva       = ffma(dva, DT, NZ);      dvb       = ffma(dvb, DT, NZ);
                Va        = ffma(dva, 1.0f, Va);    Vb        = ffma(dvb, 1.0f, Vb);

                // Thr += DT * (a*(V-EL) - B*(Thr-TINF))
                float tta = ffma(Ta, 1.0f, NTIN);   float ttb = ffma(Tb, 1.0f, NTIN);
                float v2a = ffma(Va, 1.0f, NEL);    float v2b = ffma(Vb, 1.0f, NEL);
                float t2a = ffma(tta, Bc, NZ);      float t2b = ffma(ttb, Bc, NZ);
                float t1a = ffma(a2.x, v2a, NZ);    float t1b = ffma(a2.y, v2b, NZ);
                float dda = ffma(t2a, -1.0f, t1a);  float ddb = ffma(t2b, -1.0f, t1b);
                dda       = ffma(dda, DT, NZ);      ddb       = ffma(ddb, DT, NZ);
                Ta        = ffma(dda, 1.0f, Ta);    Tb        = ffma(ddb, 1.0f, Tb);

                // spike predicate: (V - Thr) > 0 <=> V > Thr (exact)
                const bool pa = (Va > Ta);          const bool pb = (Vb > Tb);

                // reset candidates (two-rounded, as reference) + exact selects
                float c1a = ffma(i1a, R1, NZ);      float c1b = ffma(i1b, R1, NZ);
                float c2a = ffma(i2a, R2, NZ);      float c2b = ffma(i2b, R2, NZ);
                c1a = ffma(c1a, 1.0f, A12.x);       c1b = ffma(c1b, 1.0f, A12.y);
                c2a = ffma(c2a, 1.0f, A22.x);       c2b = ffma(c2b, 1.0f, A22.y);
                i1a = pa ? c1a : i1a;               i1b = pb ? c1b : i1b;
                i2a = pa ? c2a : i2a;               i2b = pb ? c2b : i2b;
                Ta  = pa ? fmaxf(Ta, TR) : Ta;      Tb  = pb ? fmaxf(Tb, TR) : Tb;
                Va  = pa ? VR : Va;                 Vb  = pb ? VR : Vb;

                float2 sp;
                sp.x = pa ? 1.0f : 0.0f;
                sp.y = pb ? 1.0f : 0.0f;
                __stcs(op + (size_t)(t0 + ph * UPF + u) * (BN / 2), sp);
            }
        }
    }
}

extern "C" void kernel_launch(void* const* d_in, const int* in_sizes, int n_in,
                              void* d_out, int out_size)
{
    const float* x   = (const float*)d_in[0];  // [T, B, N]
    const float* lin = (const float*)d_in[1];  // [1, N]
    const float* a   = (const float*)d_in[2];  // [1, N]
    const float* A1  = (const float*)d_in[3];  // [1, N]
    const float* A2  = (const float*)d_in[4];  // [1, N]
    float* out = (float*)d_out;                // [T, B, N]

    (void)in_sizes; (void)n_in; (void)out_size;

    mn_neuron_kernel<<<NT / 32, 32>>>(x, lin, a, A1, A2, out);
}